// round 7
// baseline (speedup 1.0000x reference)
#include <cuda_runtime.h>
#include <cstdint>
#include <cfloat>

// Problem constants (fixed by dataset)
#define NN    2048
#define TT    128
#define KSEL  20
#define MAXA  20
#define LRC   0.01f
#define EPSC  1e-8f
#define NW32  (NN/32)
#define MCAP  2560
#define NROWS 4
#define NPAN  (NN/NROWS)   // 512 panel tasks
#define SBST  136          // padded t-stride in sB
#define GRIDN 148          // <= SM count: wave-1 residency guaranteed

// ---------------- device scratch ---------------------------------------------
__device__ static float    g_B[(TT - 1) * NN];
__device__ static int16_t  g_act_idx[TT * MAXA];
__device__ static int      g_act_cnt[TT];
__device__ static int      g_act_cntfull[TT];
__device__ static unsigned g_act_mask[TT * NW32];
__device__ static unsigned g_match[(TT - 1) * MCAP];   // (js | s1<<8 | c2<<16)
__device__ static int      g_match_cnt[TT - 1];
__device__ static unsigned g_arrive;                   // cumulative ticket
__device__ static unsigned g_release;                  // monotonic generation

// grid-wide barrier: cumulative tickets, monotonic release (replay-safe)
__device__ __forceinline__ void gsync() {
    __syncthreads();
    if (threadIdx.x == 0) {
        __threadfence();
        const unsigned tk = atomicAdd(&g_arrive, 1u);
        const unsigned target = tk / GRIDN + 1u;
        if ((tk % GRIDN) == GRIDN - 1u) {
            atomicExch(&g_release, target);
        } else {
            unsigned r;
            do {
                asm volatile("ld.volatile.global.u32 %0, [%1];"
                             : "=r"(r) : "l"(&g_release));
            } while (r < target);
        }
        __threadfence();
    }
    __syncthreads();
}

// smem layout (one 46.3KB arena, phase-overlaid)
// phase0: hist[256]u32 @0, mask[64]u32 @1024, prefix@1280, kk@1284, cnt@1288
// phase1: panel 32768 @0, sB 2176 @32768, pos 2048 @34944, cntp @36992
// phase2: cw 40960 @0, red 64 @46208
// shared (staged in phase1, read in phase2): idx 5120 @40960, acnt 128 @46080
#define OFF_SB    32768
#define OFF_POS   34944
#define OFF_CNTP  36992
#define OFF_IDX   40960
#define OFF_ACNT  46080
#define OFF_RED   46208
#define SMEM_SZ   46272

__global__ void __launch_bounds__(256, 1)
k_fused(const int* __restrict__ tokens, const float* __restrict__ proj,
        const float* __restrict__ S, const int* __restrict__ plast,
        float* __restrict__ out) {
    __shared__ __align__(16) char s_raw[SMEM_SZ];
    const int bx   = blockIdx.x;
    const int tid  = threadIdx.x;
    const int lane = tid & 31;

    // ================= phase 0: top-K radix select (blocks 0..127) ==========
    if (bx < TT) {
        const int t    = bx;
        const int base = tid * 8;
        unsigned* hist    = reinterpret_cast<unsigned*>(s_raw);
        unsigned* smask   = reinterpret_cast<unsigned*>(s_raw + 1024);
        unsigned* sprefix = reinterpret_cast<unsigned*>(s_raw + 1280);
        int*      skk     = reinterpret_cast<int*>(s_raw + 1284);
        int*      scnt    = reinterpret_cast<int*>(s_raw + 1288);

        const float* row = proj + (size_t)tokens[t] * NN;
        const float4* rv4 = reinterpret_cast<const float4*>(row + base);
        float4 a = rv4[0], b = rv4[1];
        float v[8] = {a.x, a.y, a.z, a.w, b.x, b.y, b.z, b.w};
        unsigned key[8];
        #pragma unroll
        for (int m = 0; m < 8; m++) {
            unsigned u = __float_as_uint(v[m]);
            key[m] = (u >> 31) ? ~u : (u | 0x80000000u);
        }

        if (tid == 0) { *sprefix = 0u; *skk = KSEL; }
        unsigned prefix = 0u;
        int kk = KSEL;

        #pragma unroll
        for (int bp = 3; bp >= 0; bp--) {
            hist[tid] = 0u;
            __syncthreads();
            #pragma unroll
            for (int m = 0; m < 8; m++) {
                bool match = (bp == 3) || ((key[m] >> ((bp + 1) * 8)) == prefix);
                if (match) atomicAdd(&hist[(key[m] >> (bp * 8)) & 0xFFu], 1u);
            }
            __syncthreads();
            if (tid < 32) {
                const int top = 255 - lane * 8;
                unsigned local = 0, hv[8];
                #pragma unroll
                for (int q = 0; q < 8; q++) { hv[q] = hist[top - q]; local += hv[q]; }
                unsigned incl = local;
                #pragma unroll
                for (int o = 1; o < 32; o <<= 1) {
                    unsigned u = __shfl_up_sync(0xFFFFFFFFu, incl, o);
                    if (lane >= o) incl += u;
                }
                unsigned excl = incl - local;
                if (excl < (unsigned)kk && incl >= (unsigned)kk) {
                    unsigned e = excl;
                    #pragma unroll
                    for (int q = 0; q < 8; q++) {
                        if (e + hv[q] >= (unsigned)kk) {
                            *sprefix = (prefix << 8) | (unsigned)(top - q);
                            *skk = kk - (int)e;
                            break;
                        }
                        e += hv[q];
                    }
                }
            }
            __syncthreads();
            prefix = *sprefix;
            kk = *skk;
        }
        const unsigned key_thr = prefix;

        if (tid < NW32) smask[tid] = 0u;
        if (tid == 0)   *scnt = 0;
        __syncthreads();

        #pragma unroll
        for (int m = 0; m < 8; m++) {
            if (key[m] >= key_thr) {
                int i = base + m;
                atomicOr(&smask[i >> 5], 1u << (i & 31));
                int p = atomicAdd(scnt, 1);
                if (p < MAXA) g_act_idx[t * MAXA + p] = (int16_t)i;
            }
        }
        __syncthreads();

        const int cnt = *scnt;
        const int cc  = (cnt < MAXA) ? cnt : MAXA;
        if (tid >= cc && tid < MAXA) g_act_idx[t * MAXA + tid] = 0;
        if (tid < NW32) g_act_mask[t * NW32 + tid] = smask[tid];
        if (tid == 0) { g_act_cntfull[t] = cnt; g_act_cnt[t] = cc; }
    }

    gsync();

    // ========== phase 1: panel sums (tasks 0..511) + match lists (512..638) ==
    {
        int16_t* idx   = reinterpret_cast<int16_t*>(s_raw + OFF_IDX);
        uint8_t* acnt  = reinterpret_cast<uint8_t*>(s_raw + OFF_ACNT);
        float*   panel = reinterpret_cast<float*>(s_raw);
        float*   sB    = reinterpret_cast<float*>(s_raw + OFF_SB);
        uint8_t* pos   = reinterpret_cast<uint8_t*>(s_raw + OFF_POS);
        int*     cntp  = reinterpret_cast<int*>(s_raw + OFF_CNTP);

        for (int x = tid; x < TT * MAXA / 2; x += 256)
            reinterpret_cast<int*>(idx)[x] =
                reinterpret_cast<const int*>(g_act_idx)[x];
        if (tid < TT) acnt[tid] = (uint8_t)g_act_cnt[tid];
        __syncthreads();

        const int pl = *plast;

        for (int task = bx; task < NPAN + (TT - 1); task += GRIDN) {
            if (task < NPAN) {
                const int i0 = task * NROWS;
                #pragma unroll
                for (int il = 0; il < NROWS; il++) {
                    const float4* src = reinterpret_cast<const float4*>(
                        S + (size_t)(i0 + il) * NN);
                    float4* dst = reinterpret_cast<float4*>(panel + il * NN);
                    for (int x = tid; x < NN / 4; x += 256) dst[x] = src[x];
                }
                for (int x = tid; x < NROWS * SBST; x += 256) sB[x] = 0.f;
                __syncthreads();

                // w = m*512 + il*128 + t (conflict-free both sides)
                for (int w = tid; w < 32 * 512; w += 256) {
                    const int t  = w & 127;
                    const int il = (w >> 7) & 3;
                    const int m  = w >> 9;
                    if (t < TT - 1 && m < (int)acnt[t]) {
                        const int j = (int)idx[t * MAXA + m];
                        atomicAdd(&sB[il * SBST + t], panel[il * NN + j]);
                    }
                }
                __syncthreads();

                for (int w = tid; w < (TT - 1) * NROWS; w += 256) {
                    const int t  = w >> 2;
                    const int il = w & 3;
                    g_B[t * NN + i0 + il] = sB[il * SBST + t];
                }
                __syncthreads();     // before panel reuse
            } else if (pl) {
                const int t = task - NPAN;
                for (int x = tid; x < NN / 4; x += 256)
                    reinterpret_cast<unsigned*>(pos)[x] = 0xFFFFFFFFu;
                if (tid == 0) *cntp = 0;
                __syncthreads();
                if (tid < (int)acnt[t]) pos[(int)idx[t * MAXA + tid]] = (uint8_t)tid;
                __syncthreads();
                for (int wk = tid; wk < t * 32; wk += 256) {
                    const int s = wk >> 5;
                    const int m = wk & 31;
                    if (m < (int)acnt[s]) {
                        const int j  = (int)idx[s * MAXA + m];
                        const int js = pos[j];
                        if (js != 0xFF) {
                            const int p = atomicAdd(cntp, 1);
                            g_match[t * MCAP + p] =
                                (unsigned)js | ((unsigned)(s + 1) << 8) |
                                ((unsigned)acnt[s + 1] << 16);
                        }
                    }
                }
                __syncthreads();
                if (tid == 0) g_match_cnt[t] = *cntp;
                __syncthreads();     // before pos reuse
            }
        }
    }

    gsync();

    // ================= phase 2: tension per t (blocks 0..126) ================
    if (bx < TT - 1) {
        const int t  = bx;
        const int w  = tid >> 5;
        const int i0 = tid * 8;
        unsigned* cw  = reinterpret_cast<unsigned*>(s_raw);          // 40960 B
        int16_t*  idx = reinterpret_cast<int16_t*>(s_raw + OFF_IDX); // staged ph1
        float*    red = reinterpret_cast<float*>(s_raw + OFF_RED);

        const int pl = *plast;
        if (pl)
            for (int x = tid; x < MAXA * NN / 4; x += 256) cw[x] = 0u;

        const float4 a4 = *reinterpret_cast<const float4*>(g_B + t * NN + i0);
        const float4 b4 = *reinterpret_cast<const float4*>(g_B + t * NN + i0 + 4);
        float p[8] = {a4.x, a4.y, a4.z, a4.w, b4.x, b4.y, b4.z, b4.w};

        if (pl) {
            __syncthreads();
            const int nm = g_match_cnt[t];
            for (int e = tid; e < nm; e += 256) {
                const unsigned ent = g_match[t * MCAP + e];
                const int js = (int)(ent & 0xFFu);
                const int b2 = (int)((ent >> 8) & 0xFFu) * MAXA;
                const int c2 = (int)(ent >> 16);
                for (int mm = 0; mm < c2; mm++) {
                    const unsigned i = (unsigned)(int)idx[b2 + mm];
                    const unsigned off = (unsigned)js * NN + i;
                    atomicAdd(&cw[off >> 2], 1u << ((off & 3u) * 8u));
                }
            }
            __syncthreads();

            #pragma unroll
            for (int js = 0; js < MAXA; js++) {
                const unsigned w0 = cw[js * (NN / 4) + tid * 2];
                const unsigned w1 = cw[js * (NN / 4) + tid * 2 + 1];
                if (w0 | w1) {
                    const int j = (int)idx[t * MAXA + js];
                    #pragma unroll
                    for (int c = 0; c < 4; c++) {
                        const unsigned cc = (w0 >> (c * 8)) & 0xFFu;
                        if (cc) {
                            const float v = S[(size_t)(i0 + c) * NN + j];
                            p[c] += fminf(v + LRC * (float)cc, 1.0f) - v;
                        }
                    }
                    #pragma unroll
                    for (int c = 0; c < 4; c++) {
                        const unsigned cc = (w1 >> (c * 8)) & 0xFFu;
                        if (cc) {
                            const float v = S[(size_t)(i0 + 4 + c) * NN + j];
                            p[4 + c] += fminf(v + LRC * (float)cc, 1.0f) - v;
                        }
                    }
                }
            }
        }

        const unsigned mword = g_act_mask[(t + 1) * NW32 + (i0 >> 5)];
        const unsigned mb = (mword >> (i0 & 31)) & 0xFFu;
        float pn2 = 0.f, dt = 0.f;
        #pragma unroll
        for (int c = 0; c < 8; c++) {
            pn2 += p[c] * p[c];
            if ((mb >> c) & 1u) dt += p[c];
        }
        #pragma unroll
        for (int o = 16; o; o >>= 1) {
            pn2 += __shfl_xor_sync(0xFFFFFFFFu, pn2, o);
            dt  += __shfl_xor_sync(0xFFFFFFFFu, dt, o);
        }
        __syncthreads();
        if (lane == 0) { red[2 * w] = pn2; red[2 * w + 1] = dt; }
        __syncthreads();
        if (tid == 0) {
            float P2 = 0.f, D = 0.f;
            #pragma unroll
            for (int r = 0; r < 8; r++) { P2 += red[2 * r]; D += red[2 * r + 1]; }
            const float pn = sqrtf(P2);
            float tension;
            if (pl) {
                const float overlap = D / (pn * sqrtf((float)KSEL) + EPSC);
                tension = (pn > 0.0f) ? (1.0f - overlap) : 1.0f;
            } else {
                const float xn = sqrtf((float)g_act_cntfull[t + 1]);
                tension = 1.0f - D / (pn * xn + EPSC);
            }
            out[t] = tension;
        }
    }
}

// ---------------- launch ------------------------------------------------------
extern "C" void kernel_launch(void* const* d_in, const int* in_sizes, int n_in,
                              void* d_out, int out_size) {
    const int*   tokens = (const int*)d_in[0];
    const float* proj   = (const float*)d_in[1];
    const float* sigma  = (const float*)d_in[2];
    const int*   plast  = (const int*)d_in[3];
    float*       out    = (float*)d_out;

    k_fused<<<GRIDN, 256>>>(tokens, proj, sigma, plast, out);
}

// round 8
// speedup vs baseline: 1.8250x; 1.8250x over previous
#include <cuda_runtime.h>
#include <cstdint>
#include <cfloat>

// Problem constants (fixed by dataset)
#define NN    2048
#define TT    128
#define KSEL  20
#define MAXA  20
#define LRC   0.01f
#define EPSC  1e-8f
#define NW32  (NN/32)
#define MCAP  2560
#define NROWS 4
#define NPAN  (NN/NROWS)   // 512 panel tasks
#define PSTR  2056         // padded panel row stride (floats); 2056%32=8 -> il rows on different banks
#define GRIDN 296          // 2 CTAs/SM x 148 SMs: all resident, spin-barrier safe

// ---------------- device scratch ---------------------------------------------
__device__ static float    g_B[(TT - 1) * NN];
__device__ static int16_t  g_act_idx[TT * MAXA];
__device__ static int      g_act_cnt[TT];
__device__ static int      g_act_cntfull[TT];
__device__ static unsigned g_act_mask[TT * NW32];
__device__ static unsigned g_match[(TT - 1) * MCAP];   // (js | s1<<8 | c2<<16)
__device__ static int      g_match_cnt[TT - 1];
__device__ static unsigned g_arrive;                   // cumulative ticket
__device__ static unsigned g_release;                  // monotonic generation

// grid-wide barrier: cumulative tickets, monotonic release (graph-replay-safe)
__device__ __forceinline__ void gsync() {
    __syncthreads();
    if (threadIdx.x == 0) {
        __threadfence();
        const unsigned tk = atomicAdd(&g_arrive, 1u);
        const unsigned target = tk / GRIDN + 1u;
        if ((tk % GRIDN) == GRIDN - 1u) {
            atomicExch(&g_release, target);
        } else {
            unsigned r;
            for (;;) {
                asm volatile("ld.volatile.global.u32 %0, [%1];"
                             : "=r"(r) : "l"(&g_release));
                if (r >= target) break;
                __nanosleep(64);
            }
        }
        __threadfence();
    }
    __syncthreads();
}

// smem arena (46.3KB, phase-overlaid):
// phase0: hist[256]u32 @0, mask @1024, prefix @1280, kk @1284, cnt @1288
// phase1: panel 4*PSTR*4=32896 @0, pos 2048 @33024, cntp @35072
// phase2: cw 40960 @0, red @46208
// persistent across ph1->ph2: idx @40960 (5120), acnt @46080 (128)
#define OFF_POS   33024
#define OFF_CNTP  35072
#define OFF_IDX   40960
#define OFF_ACNT  46080
#define OFF_RED   46208
#define SMEM_SZ   46272

__global__ void __launch_bounds__(256, 2)
k_fused(const int* __restrict__ tokens, const float* __restrict__ proj,
        const float* __restrict__ S, const int* __restrict__ plast,
        float* __restrict__ out) {
    __shared__ __align__(16) char s_raw[SMEM_SZ];
    const int bx   = blockIdx.x;
    const int tid  = threadIdx.x;
    const int lane = tid & 31;

    // ================= phase 0: top-K radix select (blocks 0..127) ==========
    if (bx < TT) {
        const int t    = bx;
        const int base = tid * 8;
        unsigned* hist    = reinterpret_cast<unsigned*>(s_raw);
        unsigned* smask   = reinterpret_cast<unsigned*>(s_raw + 1024);
        unsigned* sprefix = reinterpret_cast<unsigned*>(s_raw + 1280);
        int*      skk     = reinterpret_cast<int*>(s_raw + 1284);
        int*      scnt    = reinterpret_cast<int*>(s_raw + 1288);

        const float* row = proj + (size_t)tokens[t] * NN;
        const float4* rv4 = reinterpret_cast<const float4*>(row + base);
        float4 a = rv4[0], b = rv4[1];
        float v[8] = {a.x, a.y, a.z, a.w, b.x, b.y, b.z, b.w};
        unsigned key[8];
        #pragma unroll
        for (int m = 0; m < 8; m++) {
            unsigned u = __float_as_uint(v[m]);
            key[m] = (u >> 31) ? ~u : (u | 0x80000000u);
        }

        if (tid == 0) { *sprefix = 0u; *skk = KSEL; }
        unsigned prefix = 0u;
        int kk = KSEL;

        #pragma unroll
        for (int bp = 3; bp >= 0; bp--) {
            hist[tid] = 0u;
            __syncthreads();
            #pragma unroll
            for (int m = 0; m < 8; m++) {
                bool match = (bp == 3) || ((key[m] >> ((bp + 1) * 8)) == prefix);
                if (match) atomicAdd(&hist[(key[m] >> (bp * 8)) & 0xFFu], 1u);
            }
            __syncthreads();
            if (tid < 32) {
                const int top = 255 - lane * 8;
                unsigned local = 0, hv[8];
                #pragma unroll
                for (int q = 0; q < 8; q++) { hv[q] = hist[top - q]; local += hv[q]; }
                unsigned incl = local;
                #pragma unroll
                for (int o = 1; o < 32; o <<= 1) {
                    unsigned u = __shfl_up_sync(0xFFFFFFFFu, incl, o);
                    if (lane >= o) incl += u;
                }
                unsigned excl = incl - local;
                if (excl < (unsigned)kk && incl >= (unsigned)kk) {
                    unsigned e = excl;
                    #pragma unroll
                    for (int q = 0; q < 8; q++) {
                        if (e + hv[q] >= (unsigned)kk) {
                            *sprefix = (prefix << 8) | (unsigned)(top - q);
                            *skk = kk - (int)e;
                            break;
                        }
                        e += hv[q];
                    }
                }
            }
            __syncthreads();
            prefix = *sprefix;
            kk = *skk;
        }
        const unsigned key_thr = prefix;

        if (tid < NW32) smask[tid] = 0u;
        if (tid == 0)   *scnt = 0;
        __syncthreads();

        #pragma unroll
        for (int m = 0; m < 8; m++) {
            if (key[m] >= key_thr) {
                int i = base + m;
                atomicOr(&smask[i >> 5], 1u << (i & 31));
                int p = atomicAdd(scnt, 1);
                if (p < MAXA) g_act_idx[t * MAXA + p] = (int16_t)i;
            }
        }
        __syncthreads();

        const int cnt = *scnt;
        const int cc  = (cnt < MAXA) ? cnt : MAXA;
        if (tid >= cc && tid < MAXA) g_act_idx[t * MAXA + tid] = 0;
        if (tid < NW32) g_act_mask[t * NW32 + tid] = smask[tid];
        if (tid == 0) { g_act_cntfull[t] = cnt; g_act_cnt[t] = cc; }
    }

    gsync();

    // ========= phase 1: panel sums (tasks 0..511) + match lists (512..638) ===
    {
        int16_t* idx   = reinterpret_cast<int16_t*>(s_raw + OFF_IDX);
        uint8_t* acnt  = reinterpret_cast<uint8_t*>(s_raw + OFF_ACNT);
        float*   panel = reinterpret_cast<float*>(s_raw);
        uint8_t* pos   = reinterpret_cast<uint8_t*>(s_raw + OFF_POS);
        int*     cntp  = reinterpret_cast<int*>(s_raw + OFF_CNTP);

        for (int x = tid; x < TT * MAXA / 2; x += 256)
            reinterpret_cast<int*>(idx)[x] =
                reinterpret_cast<const int*>(g_act_idx)[x];
        if (tid < TT) acnt[tid] = (uint8_t)g_act_cnt[tid];
        __syncthreads();

        const int pl = *plast;

        for (int task = bx; task < NPAN + (TT - 1); task += GRIDN) {
            if (task < NPAN) {
                const int i0 = task * NROWS;
                #pragma unroll
                for (int il = 0; il < NROWS; il++) {
                    const float4* src = reinterpret_cast<const float4*>(
                        S + (size_t)(i0 + il) * NN);
                    float4* dst = reinterpret_cast<float4*>(panel + il * PSTR);
                    for (int x = tid; x < NN / 4; x += 256) dst[x] = src[x];
                }
                __syncthreads();

                // atomic-free: thread owns (t, il); 20 LDS + 20 FADD
                for (int w2 = tid; w2 < (TT - 1) * NROWS; w2 += 256) {
                    const int t  = w2 >> 2;
                    const int il = w2 & 3;
                    const float* prow = panel + il * PSTR;
                    const int cnt = (int)acnt[t];
                    float sum = 0.f;
                    #pragma unroll
                    for (int m = 0; m < MAXA; m++) {
                        const int j = (int)idx[t * MAXA + m];
                        if (m < cnt) sum += prow[j];
                    }
                    g_B[t * NN + i0 + il] = sum;
                }
                __syncthreads();     // before panel reuse
            } else if (pl) {
                const int t = task - NPAN;
                for (int x = tid; x < NN / 4; x += 256)
                    reinterpret_cast<unsigned*>(pos)[x] = 0xFFFFFFFFu;
                if (tid == 0) *cntp = 0;
                __syncthreads();
                if (tid < (int)acnt[t]) pos[(int)idx[t * MAXA + tid]] = (uint8_t)tid;
                __syncthreads();
                for (int wk = tid; wk < t * 32; wk += 256) {
                    const int s = wk >> 5;
                    const int m = wk & 31;
                    if (m < (int)acnt[s]) {
                        const int j  = (int)idx[s * MAXA + m];
                        const int js = pos[j];
                        if (js != 0xFF) {
                            const int p = atomicAdd(cntp, 1);
                            g_match[t * MCAP + p] =
                                (unsigned)js | ((unsigned)(s + 1) << 8) |
                                ((unsigned)acnt[s + 1] << 16);
                        }
                    }
                }
                __syncthreads();
                if (tid == 0) g_match_cnt[t] = *cntp;
                __syncthreads();     // before pos reuse
            }
        }
    }

    gsync();

    // ================= phase 2: tension per t (blocks 0..126) ================
    if (bx < TT - 1) {
        const int t  = bx;
        const int w  = tid >> 5;
        const int i0 = tid * 8;
        unsigned* cw  = reinterpret_cast<unsigned*>(s_raw);          // 40960 B
        int16_t*  idx = reinterpret_cast<int16_t*>(s_raw + OFF_IDX); // staged ph1
        float*    red = reinterpret_cast<float*>(s_raw + OFF_RED);

        const int pl = *plast;
        if (pl)
            for (int x = tid; x < MAXA * NN / 4; x += 256) cw[x] = 0u;

        const float4 a4 = *reinterpret_cast<const float4*>(g_B + t * NN + i0);
        const float4 b4 = *reinterpret_cast<const float4*>(g_B + t * NN + i0 + 4);
        float p[8] = {a4.x, a4.y, a4.z, a4.w, b4.x, b4.y, b4.z, b4.w};

        if (pl) {
            __syncthreads();
            const int nm = g_match_cnt[t];
            for (int e = tid; e < nm; e += 256) {
                const unsigned ent = g_match[t * MCAP + e];
                const int js = (int)(ent & 0xFFu);
                const int b2 = (int)((ent >> 8) & 0xFFu) * MAXA;
                const int c2 = (int)(ent >> 16);
                for (int mm = 0; mm < c2; mm++) {
                    const unsigned i = (unsigned)(int)idx[b2 + mm];
                    const unsigned off = (unsigned)js * NN + i;
                    atomicAdd(&cw[off >> 2], 1u << ((off & 3u) * 8u));
                }
            }
            __syncthreads();

            #pragma unroll
            for (int js = 0; js < MAXA; js++) {
                const unsigned w0 = cw[js * (NN / 4) + tid * 2];
                const unsigned w1 = cw[js * (NN / 4) + tid * 2 + 1];
                if (w0 | w1) {
                    const int j = (int)idx[t * MAXA + js];
                    #pragma unroll
                    for (int c = 0; c < 4; c++) {
                        const unsigned cc = (w0 >> (c * 8)) & 0xFFu;
                        if (cc) {
                            const float v = S[(size_t)(i0 + c) * NN + j];
                            p[c] += fminf(v + LRC * (float)cc, 1.0f) - v;
                        }
                    }
                    #pragma unroll
                    for (int c = 0; c < 4; c++) {
                        const unsigned cc = (w1 >> (c * 8)) & 0xFFu;
                        if (cc) {
                            const float v = S[(size_t)(i0 + 4 + c) * NN + j];
                            p[4 + c] += fminf(v + LRC * (float)cc, 1.0f) - v;
                        }
                    }
                }
            }
        }

        const unsigned mword = g_act_mask[(t + 1) * NW32 + (i0 >> 5)];
        const unsigned mb = (mword >> (i0 & 31)) & 0xFFu;
        float pn2 = 0.f, dt = 0.f;
        #pragma unroll
        for (int c = 0; c < 8; c++) {
            pn2 += p[c] * p[c];
            if ((mb >> c) & 1u) dt += p[c];
        }
        #pragma unroll
        for (int o = 16; o; o >>= 1) {
            pn2 += __shfl_xor_sync(0xFFFFFFFFu, pn2, o);
            dt  += __shfl_xor_sync(0xFFFFFFFFu, dt, o);
        }
        __syncthreads();
        if (lane == 0) { red[2 * w] = pn2; red[2 * w + 1] = dt; }
        __syncthreads();
        if (tid == 0) {
            float P2 = 0.f, D = 0.f;
            #pragma unroll
            for (int r = 0; r < 8; r++) { P2 += red[2 * r]; D += red[2 * r + 1]; }
            const float pn = sqrtf(P2);
            float tension;
            if (pl) {
                const float overlap = D / (pn * sqrtf((float)KSEL) + EPSC);
                tension = (pn > 0.0f) ? (1.0f - overlap) : 1.0f;
            } else {
                const float xn = sqrtf((float)g_act_cntfull[t + 1]);
                tension = 1.0f - D / (pn * xn + EPSC);
            }
            out[t] = tension;
        }
    }
}

// ---------------- launch ------------------------------------------------------
extern "C" void kernel_launch(void* const* d_in, const int* in_sizes, int n_in,
                              void* d_out, int out_size) {
    const int*   tokens = (const int*)d_in[0];
    const float* proj   = (const float*)d_in[1];
    const float* sigma  = (const float*)d_in[2];
    const int*   plast  = (const int*)d_in[3];
    float*       out    = (float*)d_out;

    k_fused<<<GRIDN, 256>>>(tokens, proj, sigma, plast, out);
}

// round 10
// speedup vs baseline: 2.1226x; 1.1631x over previous
#include <cuda_runtime.h>
#include <cstdint>
#include <cfloat>

// Problem constants (fixed by dataset)
#define NN    2048
#define TT    128
#define KSEL  20
#define MAXA  20
#define LRC   0.01f
#define EPSC  1e-8f
#define NW32  (NN/32)
#define MCAP  2560
#define NROWS 4
#define NPAN  (NN/NROWS)   // 512 panel tasks
#define PSTR  2056         // padded panel row stride (floats)
#define GRIDN 148          // 1 CTA/SM, wave-1 residency guaranteed
#define NTHR  512

// ---------------- device scratch ---------------------------------------------
__device__ static float    g_B[(TT - 1) * NN];
__device__ static int16_t  g_act_idx[TT * MAXA];
__device__ static int      g_act_cnt[TT];
__device__ static int      g_act_cntfull[TT];
__device__ static unsigned g_act_mask[TT * NW32];
__device__ static unsigned g_match[(TT - 1) * MCAP];   // (js | s1<<8 | c2<<16)
__device__ static int      g_match_cnt[TT - 1];
__device__ static unsigned g_arrive;                   // cumulative ticket
__device__ static unsigned g_release;                  // monotonic generation

// grid-wide barrier: cumulative tickets, monotonic release (graph-replay-safe)
__device__ __forceinline__ void gsync() {
    __syncthreads();
    if (threadIdx.x == 0) {
        __threadfence();
        const unsigned tk = atomicAdd(&g_arrive, 1u);
        const unsigned target = tk / GRIDN + 1u;
        if ((tk % GRIDN) == GRIDN - 1u) {
            atomicExch(&g_release, target);
        } else {
            unsigned r;
            for (;;) {
                asm volatile("ld.volatile.global.u32 %0, [%1];"
                             : "=r"(r) : "l"(&g_release));
                if (r >= target) break;
                __nanosleep(64);
            }
        }
        __threadfence();
    }
    __syncthreads();
}

// smem arena (46.3KB, phase-overlaid):
// phase0: hist[256]u32 @0, mask @1024 (256B), prefix/kk/cnt @1280
// phase1: panel 4*PSTR*4 = 32896 @0, pos 2048 @33024, cntp @35072
// phase2: cw 40960 @0, red 128 @46208
// persistent ph1->ph2: idx 5120 @40960, acnt 128 @46080
#define OFF_POS   33024
#define OFF_CNTP  35072
#define OFF_IDX   40960
#define OFF_ACNT  46080
#define OFF_RED   46208
#define SMEM_SZ   46336

__global__ void __launch_bounds__(NTHR, 1)
k_fused(const int* __restrict__ tokens, const float* __restrict__ proj,
        const float* __restrict__ S, const int* __restrict__ plast,
        float* __restrict__ out) {
    __shared__ __align__(16) char s_raw[SMEM_SZ];
    const int bx   = blockIdx.x;
    const int tid  = threadIdx.x;
    const int lane = tid & 31;

    // ================= phase 0: top-K radix select (blocks 0..127) ==========
    if (bx < TT) {
        const int t    = bx;
        const int base = tid * 4;
        unsigned* hist    = reinterpret_cast<unsigned*>(s_raw);
        unsigned* smask   = reinterpret_cast<unsigned*>(s_raw + 1024);
        unsigned* sprefix = reinterpret_cast<unsigned*>(s_raw + 1280);
        int*      skk     = reinterpret_cast<int*>(s_raw + 1284);
        int*      scnt    = reinterpret_cast<int*>(s_raw + 1288);

        const float* row = proj + (size_t)tokens[t] * NN;
        const float4 a = *reinterpret_cast<const float4*>(row + base);
        const float v[4] = {a.x, a.y, a.z, a.w};
        unsigned key[4];
        #pragma unroll
        for (int m = 0; m < 4; m++) {
            unsigned u = __float_as_uint(v[m]);
            key[m] = (u >> 31) ? ~u : (u | 0x80000000u);
        }

        if (tid == 0) { *sprefix = 0u; *skk = KSEL; }
        unsigned prefix = 0u;
        int kk = KSEL;

        #pragma unroll
        for (int bp = 3; bp >= 0; bp--) {
            if (tid < 256) hist[tid] = 0u;
            __syncthreads();
            #pragma unroll
            for (int m = 0; m < 4; m++) {
                const bool match =
                    (bp == 3) || ((key[m] >> ((bp + 1) * 8)) == prefix);
                const unsigned bin =
                    match ? ((key[m] >> (bp * 8)) & 0xFFu) : 0x1FFu;
                const unsigned mk = __match_any_sync(0xFFFFFFFFu, bin);
                if (match && lane == (__ffs(mk) - 1))
                    atomicAdd(&hist[bin], (unsigned)__popc(mk));
            }
            __syncthreads();
            if (tid < 32) {
                const int top = 255 - lane * 8;
                unsigned local = 0, hv[8];
                #pragma unroll
                for (int q = 0; q < 8; q++) { hv[q] = hist[top - q]; local += hv[q]; }
                unsigned incl = local;
                #pragma unroll
                for (int o = 1; o < 32; o <<= 1) {
                    unsigned u = __shfl_up_sync(0xFFFFFFFFu, incl, o);
                    if (lane >= o) incl += u;
                }
                unsigned excl = incl - local;
                if (excl < (unsigned)kk && incl >= (unsigned)kk) {
                    unsigned e = excl;
                    #pragma unroll
                    for (int q = 0; q < 8; q++) {
                        if (e + hv[q] >= (unsigned)kk) {
                            *sprefix = (prefix << 8) | (unsigned)(top - q);
                            *skk = kk - (int)e;
                            break;
                        }
                        e += hv[q];
                    }
                }
            }
            __syncthreads();
            prefix = *sprefix;
            kk = *skk;
        }
        const unsigned key_thr = prefix;

        if (tid < NW32) smask[tid] = 0u;
        if (tid == 0)   *scnt = 0;
        __syncthreads();

        #pragma unroll
        for (int m = 0; m < 4; m++) {
            if (key[m] >= key_thr) {
                int i = base + m;
                atomicOr(&smask[i >> 5], 1u << (i & 31));
                int p = atomicAdd(scnt, 1);
                if (p < MAXA) g_act_idx[t * MAXA + p] = (int16_t)i;
            }
        }
        __syncthreads();

        const int cnt = *scnt;
        const int cc  = (cnt < MAXA) ? cnt : MAXA;
        if (tid >= cc && tid < MAXA) g_act_idx[t * MAXA + tid] = 0;
        if (tid < NW32) g_act_mask[t * NW32 + tid] = smask[tid];
        if (tid == 0) { g_act_cntfull[t] = cnt; g_act_cnt[t] = cc; }
    }

    gsync();

    // ========= phase 1: panel sums (tasks 0..511) + match lists (512..638) ===
    {
        int16_t* idx   = reinterpret_cast<int16_t*>(s_raw + OFF_IDX);
        uint8_t* acnt  = reinterpret_cast<uint8_t*>(s_raw + OFF_ACNT);
        float*   panel = reinterpret_cast<float*>(s_raw);
        uint8_t* pos   = reinterpret_cast<uint8_t*>(s_raw + OFF_POS);
        int*     cntp  = reinterpret_cast<int*>(s_raw + OFF_CNTP);

        for (int x = tid; x < TT * MAXA / 2; x += NTHR)
            reinterpret_cast<int*>(idx)[x] =
                reinterpret_cast<const int*>(g_act_idx)[x];
        if (tid < TT) acnt[tid] = (uint8_t)g_act_cnt[tid];
        __syncthreads();

        const int pl = *plast;

        // each thread permanently owns one (t, il) output
        const int  my_t   = tid >> 2;
        const int  my_il  = tid & 3;
        const bool owner  = tid < (TT - 1) * NROWS;
        int my_cnt = 0;
        int jreg[MAXA];
        if (owner) {
            my_cnt = (int)acnt[my_t];
            #pragma unroll
            for (int m = 0; m < MAXA; m++)
                jreg[m] = (int)idx[my_t * MAXA + m];
        }
        const float* prow = panel + my_il * PSTR;
        __syncthreads();

        const int srow = tid >> 7;          // staging: row 0..3
        const int scol = (tid & 127) * 4;   // col group within 512-col slab

        for (int task = bx; task < NPAN + (TT - 1); task += GRIDN) {
            if (task < NPAN) {
                const int i0 = task * NROWS;
                // stage 4 full sigma rows: 4 float4s per thread (coalesced)
                #pragma unroll
                for (int k = 0; k < 4; k++) {
                    const float4 sv = *reinterpret_cast<const float4*>(
                        S + (size_t)(i0 + srow) * NN + scol + k * 512);
                    *reinterpret_cast<float4*>(
                        panel + srow * PSTR + scol + k * 512) = sv;
                }
                __syncthreads();

                if (owner) {
                    float sum = 0.f;
                    #pragma unroll
                    for (int m = 0; m < MAXA; m++) {
                        const float val = prow[jreg[m]];
                        if (m < my_cnt) sum += val;
                    }
                    g_B[my_t * NN + i0 + my_il] = sum;
                }
                __syncthreads();     // before panel reuse
            } else if (pl) {
                const int t = task - NPAN;
                for (int x = tid; x < NN / 4; x += NTHR)
                    reinterpret_cast<unsigned*>(pos)[x] = 0xFFFFFFFFu;
                if (tid == 0) *cntp = 0;
                __syncthreads();
                if (tid < (int)acnt[t]) pos[(int)idx[t * MAXA + tid]] = (uint8_t)tid;
                __syncthreads();
                for (int wk = tid; wk < t * 32; wk += NTHR) {
                    const int s = wk >> 5;
                    const int m = wk & 31;
                    if (m < (int)acnt[s]) {
                        const int j  = (int)idx[s * MAXA + m];
                        const int js = pos[j];
                        if (js != 0xFF) {
                            const int p = atomicAdd(cntp, 1);
                            g_match[t * MCAP + p] =
                                (unsigned)js | ((unsigned)(s + 1) << 8) |
                                ((unsigned)acnt[s + 1] << 16);
                        }
                    }
                }
                __syncthreads();
                if (tid == 0) g_match_cnt[t] = *cntp;
                __syncthreads();     // before pos reuse
            }
        }
    }

    gsync();

    // ================= phase 2: tension per t (blocks 0..126) ================
    if (bx < TT - 1) {
        const int t  = bx;
        const int w  = tid >> 5;
        const int i0 = tid * 4;
        unsigned* cw  = reinterpret_cast<unsigned*>(s_raw);          // 40960 B
        int16_t*  idx = reinterpret_cast<int16_t*>(s_raw + OFF_IDX); // staged ph1
        float*    red = reinterpret_cast<float*>(s_raw + OFF_RED);

        const int pl = *plast;
        if (pl)
            for (int x = tid; x < MAXA * NN / 4; x += NTHR) cw[x] = 0u;

        const float4 a4 = *reinterpret_cast<const float4*>(g_B + t * NN + i0);
        float p[4] = {a4.x, a4.y, a4.z, a4.w};

        if (pl) {
            __syncthreads();
            const int nm = g_match_cnt[t];
            for (int e = tid; e < nm; e += NTHR) {
                const unsigned ent = g_match[t * MCAP + e];
                const int js = (int)(ent & 0xFFu);
                const int b2 = (int)((ent >> 8) & 0xFFu) * MAXA;
                const int c2 = (int)(ent >> 16);
                for (int mm = 0; mm < c2; mm++) {
                    const unsigned i = (unsigned)(int)idx[b2 + mm];
                    const unsigned off = (unsigned)js * NN + i;
                    atomicAdd(&cw[off >> 2], 1u << ((off & 3u) * 8u));
                }
            }
            __syncthreads();

            #pragma unroll
            for (int js = 0; js < MAXA; js++) {
                const unsigned w0 = cw[js * (NN / 4) + tid];
                if (w0) {
                    const int j = (int)idx[t * MAXA + js];
                    #pragma unroll
                    for (int c = 0; c < 4; c++) {
                        const unsigned cc = (w0 >> (c * 8)) & 0xFFu;
                        if (cc) {
                            const float v = S[(size_t)(i0 + c) * NN + j];
                            p[c] += fminf(v + LRC * (float)cc, 1.0f) - v;
                        }
                    }
                }
            }
        }

        const unsigned mword = g_act_mask[(t + 1) * NW32 + (i0 >> 5)];
        const unsigned nib = (mword >> (i0 & 31)) & 0xFu;
        float pn2 = 0.f, dt = 0.f;
        #pragma unroll
        for (int c = 0; c < 4; c++) {
            pn2 += p[c] * p[c];
            if ((nib >> c) & 1u) dt += p[c];
        }
        #pragma unroll
        for (int o = 16; o; o >>= 1) {
            pn2 += __shfl_xor_sync(0xFFFFFFFFu, pn2, o);
            dt  += __shfl_xor_sync(0xFFFFFFFFu, dt, o);
        }
        __syncthreads();
        if (lane == 0) { red[2 * w] = pn2; red[2 * w + 1] = dt; }
        __syncthreads();
        if (tid == 0) {
            float P2 = 0.f, D = 0.f;
            #pragma unroll
            for (int r = 0; r < 16; r++) { P2 += red[2 * r]; D += red[2 * r + 1]; }
            const float pn = sqrtf(P2);
            float tension;
            if (pl) {
                const float overlap = D / (pn * sqrtf((float)KSEL) + EPSC);
                tension = (pn > 0.0f) ? (1.0f - overlap) : 1.0f;
            } else {
                const float xn = sqrtf((float)g_act_cntfull[t + 1]);
                tension = 1.0f - D / (pn * xn + EPSC);
            }
            out[t] = tension;
        }
    }
}

// ---------------- launch ------------------------------------------------------
extern "C" void kernel_launch(void* const* d_in, const int* in_sizes, int n_in,
                              void* d_out, int out_size) {
    const int*   tokens = (const int*)d_in[0];
    const float* proj   = (const float*)d_in[1];
    const float* sigma  = (const float*)d_in[2];
    const int*   plast  = (const int*)d_in[3];
    float*       out    = (float*)d_out;

    k_fused<<<GRIDN, NTHR>>>(tokens, proj, sigma, plast, out);
}

// round 11
// speedup vs baseline: 2.3319x; 1.0986x over previous
#include <cuda_runtime.h>
#include <cstdint>
#include <cfloat>

// Problem constants (fixed by dataset)
#define NN    2048
#define TT    128
#define KSEL  20
#define MAXA  20
#define LRC   0.01f
#define EPSC  1e-8f
#define NW32  (NN/32)
#define MCAP  2560
#define NROWS 4
#define NPAN  (NN/NROWS)   // 512 panel blocks
#define PSTR  2056         // padded panel row stride (floats)

// ---------------- device scratch ---------------------------------------------
__device__ static float    g_B[(TT - 1) * NN];
__device__ static int16_t  g_act_idx[TT * MAXA];
__device__ static int      g_act_cnt[TT];
__device__ static int      g_act_cntfull[TT];
__device__ static unsigned g_act_mask[TT * NW32];
__device__ static unsigned g_match[(TT - 1) * MCAP];   // (js | s1<<8 | c2<<16)
__device__ static int      g_match_cnt[TT - 1];

// ================= K1: top-K radix select, warp-aggregated histogram =========
__global__ void __launch_bounds__(512)
k_topk(const int* __restrict__ tokens, const float* __restrict__ proj) {
    const int t    = blockIdx.x;
    const int tid  = threadIdx.x;
    const int lane = tid & 31;
    const int base = tid * 4;

    __shared__ unsigned hist[256];
    __shared__ unsigned smask[NW32];
    __shared__ unsigned sprefix;
    __shared__ int      skk, scnt;

    const float* row = proj + (size_t)tokens[t] * NN;
    const float4 a = *reinterpret_cast<const float4*>(row + base);
    const float v[4] = {a.x, a.y, a.z, a.w};
    unsigned key[4];
    #pragma unroll
    for (int m = 0; m < 4; m++) {
        unsigned u = __float_as_uint(v[m]);
        key[m] = (u >> 31) ? ~u : (u | 0x80000000u);
    }

    if (tid == 0) { sprefix = 0u; skk = KSEL; }
    unsigned prefix = 0u;
    int kk = KSEL;

    #pragma unroll
    for (int bp = 3; bp >= 0; bp--) {
        if (tid < 256) hist[tid] = 0u;
        __syncthreads();
        #pragma unroll
        for (int m = 0; m < 4; m++) {
            const bool match =
                (bp == 3) || ((key[m] >> ((bp + 1) * 8)) == prefix);
            const unsigned bin =
                match ? ((key[m] >> (bp * 8)) & 0xFFu) : 0x1FFu;
            const unsigned mk = __match_any_sync(0xFFFFFFFFu, bin);
            if (match && lane == (__ffs(mk) - 1))
                atomicAdd(&hist[bin], (unsigned)__popc(mk));
        }
        __syncthreads();
        if (tid < 32) {
            const int top = 255 - lane * 8;
            unsigned local = 0, hv[8];
            #pragma unroll
            for (int q = 0; q < 8; q++) { hv[q] = hist[top - q]; local += hv[q]; }
            unsigned incl = local;
            #pragma unroll
            for (int o = 1; o < 32; o <<= 1) {
                unsigned u = __shfl_up_sync(0xFFFFFFFFu, incl, o);
                if (lane >= o) incl += u;
            }
            unsigned excl = incl - local;
            if (excl < (unsigned)kk && incl >= (unsigned)kk) {
                unsigned e = excl;
                #pragma unroll
                for (int q = 0; q < 8; q++) {
                    if (e + hv[q] >= (unsigned)kk) {
                        sprefix = (prefix << 8) | (unsigned)(top - q);
                        skk = kk - (int)e;
                        break;
                    }
                    e += hv[q];
                }
            }
        }
        __syncthreads();
        prefix = sprefix;
        kk = skk;
    }
    const unsigned key_thr = prefix;

    if (tid < NW32) smask[tid] = 0u;
    if (tid == 0)   scnt = 0;
    __syncthreads();

    #pragma unroll
    for (int m = 0; m < 4; m++) {
        if (key[m] >= key_thr) {
            int i = base + m;
            atomicOr(&smask[i >> 5], 1u << (i & 31));
            int p = atomicAdd(&scnt, 1);
            if (p < MAXA) g_act_idx[t * MAXA + p] = (int16_t)i;
        }
    }
    __syncthreads();

    const int cnt = scnt;
    const int cc  = (cnt < MAXA) ? cnt : MAXA;
    if (tid >= cc && tid < MAXA) g_act_idx[t * MAXA + tid] = 0;  // pad for unroll
    if (tid < NW32) g_act_mask[t * NW32 + tid] = smask[tid];
    if (tid == 0) { g_act_cntfull[t] = cnt; g_act_cnt[t] = cc; }
}

// ====== K2: blocks 0..511 = panel sums -> g_B ; blocks 512..638 = match lists =
__global__ void __launch_bounds__(512)
k_mid(const float* __restrict__ S, const int* __restrict__ plast) {
    const int bx  = blockIdx.x;
    const int tid = threadIdx.x;
    __shared__ __align__(16) char s_raw[40832];
    // panel 32896 @0 | idx 5120 @32896 | acnt 128 @38016 | pos 2048 @38144 | cntp @40192
    float*   panel = reinterpret_cast<float*>(s_raw);
    int16_t* idx   = reinterpret_cast<int16_t*>(s_raw + 32896);
    uint8_t* acnt  = reinterpret_cast<uint8_t*>(s_raw + 38016);
    uint8_t* pos   = reinterpret_cast<uint8_t*>(s_raw + 38144);
    int*     cntp  = reinterpret_cast<int*>(s_raw + 40192);

    for (int x = tid; x < TT * MAXA / 2; x += 512)
        reinterpret_cast<int*>(idx)[x] = reinterpret_cast<const int*>(g_act_idx)[x];
    if (tid < TT) acnt[tid] = (uint8_t)g_act_cnt[tid];

    if (bx < NPAN) {
        // ---- one block per 4-row sigma panel ----
        const int i0   = bx * NROWS;
        const int srow = tid >> 7;
        const int scol = (tid & 127) * 4;
        #pragma unroll
        for (int k = 0; k < 4; k++) {
            const float4 sv = *reinterpret_cast<const float4*>(
                S + (size_t)(i0 + srow) * NN + scol + k * 512);
            *reinterpret_cast<float4*>(panel + srow * PSTR + scol + k * 512) = sv;
        }
        __syncthreads();

        if (tid < (TT - 1) * NROWS) {
            const int my_t  = tid >> 2;
            const int my_il = tid & 3;
            const int cnt   = (int)acnt[my_t];
            const float* prow = panel + my_il * PSTR;
            int jreg[MAXA];
            #pragma unroll
            for (int m = 0; m < MAXA; m++) jreg[m] = (int)idx[my_t * MAXA + m];
            float sum = 0.f;
            #pragma unroll
            for (int m = 0; m < MAXA; m++) {
                const float val = prow[jreg[m]];
                if (m < cnt) sum += val;
            }
            g_B[my_t * NN + i0 + my_il] = sum;
        }
        return;
    }

    // ---- match list for t = bx - NPAN ----
    const int t = bx - NPAN;
    if (!*plast) { if (tid == 0) g_match_cnt[t] = 0; return; }
    for (int x = tid; x < NN / 4; x += 512)
        reinterpret_cast<unsigned*>(pos)[x] = 0xFFFFFFFFu;
    if (tid == 0) *cntp = 0;
    __syncthreads();
    if (tid < (int)acnt[t]) pos[(int)idx[t * MAXA + tid]] = (uint8_t)tid;
    __syncthreads();
    for (int wk = tid; wk < t * 32; wk += 512) {
        const int s = wk >> 5;
        const int m = wk & 31;
        if (m < (int)acnt[s]) {
            const int j  = (int)idx[s * MAXA + m];
            const int js = pos[j];
            if (js != 0xFF) {
                const int p = atomicAdd(cntp, 1);
                g_match[t * MCAP + p] =
                    (unsigned)js | ((unsigned)(s + 1) << 8) |
                    ((unsigned)acnt[s + 1] << 16);
            }
        }
    }
    __syncthreads();
    if (tid == 0) g_match_cnt[t] = *cntp;
}

// ================= K3: tension, one block per t (full row, no combine) =======
__global__ void __launch_bounds__(512)
k_tension(const float* __restrict__ S, const int* __restrict__ plast,
          float* __restrict__ out) {
    const int t    = blockIdx.x;
    const int tid  = threadIdx.x;
    const int lane = tid & 31;
    const int w    = tid >> 5;
    const int i0   = tid * 4;

    __shared__ __align__(16) char s_raw[46336];
    // cw 40960 @0 | idx 5120 @40960 | red 128 @46080
    unsigned* cw  = reinterpret_cast<unsigned*>(s_raw);
    int16_t*  idx = reinterpret_cast<int16_t*>(s_raw + 40960);
    float*    red = reinterpret_cast<float*>(s_raw + 46080);

    const int pl = *plast;

    for (int x = tid; x < TT * MAXA / 2; x += 512)
        reinterpret_cast<int*>(idx)[x] = reinterpret_cast<const int*>(g_act_idx)[x];
    if (pl)
        for (int x = tid; x < MAXA * NN / 4; x += 512) cw[x] = 0u;

    const float4 a4 = *reinterpret_cast<const float4*>(g_B + t * NN + i0);
    float p[4] = {a4.x, a4.y, a4.z, a4.w};

    if (pl) {
        __syncthreads();
        const int nm = g_match_cnt[t];
        for (int e = tid; e < nm; e += 512) {
            const unsigned ent = g_match[t * MCAP + e];
            const int js = (int)(ent & 0xFFu);
            const int b2 = (int)((ent >> 8) & 0xFFu) * MAXA;
            const int c2 = (int)(ent >> 16);
            for (int mm = 0; mm < c2; mm++) {
                const unsigned i = (unsigned)(int)idx[b2 + mm];
                const unsigned off = (unsigned)js * NN + i;
                atomicAdd(&cw[off >> 2], 1u << ((off & 3u) * 8u));
            }
        }
        __syncthreads();

        #pragma unroll
        for (int js = 0; js < MAXA; js++) {
            const unsigned w0 = cw[js * (NN / 4) + tid];
            if (w0) {
                const int j = (int)idx[t * MAXA + js];
                #pragma unroll
                for (int c = 0; c < 4; c++) {
                    const unsigned cc = (w0 >> (c * 8)) & 0xFFu;
                    if (cc) {
                        const float v = S[(size_t)(i0 + c) * NN + j];
                        p[c] += fminf(v + LRC * (float)cc, 1.0f) - v;
                    }
                }
            }
        }
    }

    const unsigned mword = g_act_mask[(t + 1) * NW32 + (i0 >> 5)];
    const unsigned nib = (mword >> (i0 & 31)) & 0xFu;
    float pn2 = 0.f, dt = 0.f;
    #pragma unroll
    for (int c = 0; c < 4; c++) {
        pn2 += p[c] * p[c];
        if ((nib >> c) & 1u) dt += p[c];
    }
    #pragma unroll
    for (int o = 16; o; o >>= 1) {
        pn2 += __shfl_xor_sync(0xFFFFFFFFu, pn2, o);
        dt  += __shfl_xor_sync(0xFFFFFFFFu, dt, o);
    }
    __syncthreads();
    if (lane == 0) { red[2 * w] = pn2; red[2 * w + 1] = dt; }
    __syncthreads();
    if (tid == 0) {
        float P2 = 0.f, D = 0.f;
        #pragma unroll
        for (int r = 0; r < 16; r++) { P2 += red[2 * r]; D += red[2 * r + 1]; }
        const float pn = sqrtf(P2);
        float tension;
        if (pl) {
            const float overlap = D / (pn * sqrtf((float)KSEL) + EPSC);
            tension = (pn > 0.0f) ? (1.0f - overlap) : 1.0f;
        } else {
            const float xn = sqrtf((float)g_act_cntfull[t + 1]);
            tension = 1.0f - D / (pn * xn + EPSC);
        }
        out[t] = tension;
    }
}

// ---------------- launch ------------------------------------------------------
extern "C" void kernel_launch(void* const* d_in, const int* in_sizes, int n_in,
                              void* d_out, int out_size) {
    const int*   tokens = (const int*)d_in[0];
    const float* proj   = (const float*)d_in[1];
    const float* sigma  = (const float*)d_in[2];
    const int*   plast  = (const int*)d_in[3];
    float*       out    = (float*)d_out;

    k_topk<<<TT, 512>>>(tokens, proj);
    k_mid<<<NPAN + (TT - 1), 512>>>(sigma, plast);
    k_tension<<<TT - 1, 512>>>(sigma, plast, out);
}